// round 2
// baseline (speedup 1.0000x reference)
#include <cuda_runtime.h>
#include <math.h>

// WaterNetModel, chunk-parallel scan formulation.
// NT=1096 timesteps split into C=8 chunks of L=137.
// Snow bucket: max-plus linear recurrence  s' = max(s + a, b)  -> composable.
// Linear bucket: h' = c*(h + xin), constant c -> affine composable.
// Outputs in d_out: Q [NT,NS] | H [NT,NS,NH] | S [NT,NS,NH].

#define NT 1096
#define NS 2048
#define NH 16
#define C  8
#define L  137            // NT / C
#define LANES (NS * NH)   // 32768

// scratch (no cudaMalloc allowed)
__device__ float g_A[C * LANES];       // snow compose: slope offset
__device__ float g_B[C * LANES];       // snow compose: floor
__device__ float g_sstart[C * LANES];  // chunk-start snow state
__device__ float g_D[C * LANES];       // h chunk offset
__device__ float g_hstart[C * LANES];  // chunk-start bucket state

// ---------------------------------------------------------------- phase 1
__global__ __launch_bounds__(256)
void k1_snow_compose(const float* __restrict__ P, const float* __restrict__ T,
                     const float* __restrict__ w_s)
{
    const int g     = blockIdx.x * blockDim.x + threadIdx.x;   // [0, C*LANES)
    const int lane  = g & (LANES - 1);
    const int chunk = g >> 15;
    const int h     = lane & (NH - 1);
    const int site  = lane >> 4;

    const float melt = expf(w_s[h]) + 1.0f;

    float A = 0.0f;
    float B = -INFINITY;
    const int t0 = chunk * L;
    const float* Pp = P + site;
    const float* Tp = T + site;

    #pragma unroll 4
    for (int k = 0; k < L; k++) {
        const float Tk = __ldg(Tp + (t0 + k) * NS);
        const float Pk = __ldg(Pp + (t0 + k) * NS);
        const float sm   = fmaxf(Tk, 0.0f) * melt;
        const float pneg = (Tk < 0.0f) ? Pk : 0.0f;
        const float a = pneg - sm;
        A += a;
        B = fmaxf(B + a, pneg);
    }
    g_A[g] = A;
    g_B[g] = B;
}

// ---------------------------------------------------------------- phase 2
__global__ __launch_bounds__(256)
void k2_snow_starts()
{
    const int lane = blockIdx.x * blockDim.x + threadIdx.x;    // [0, LANES)
    float s = 0.0f;
    #pragma unroll
    for (int c = 0; c < C; c++) {
        const int i = c * LANES + lane;
        g_sstart[i] = s;
        s = fmaxf(s + g_A[i], g_B[i]);
    }
}

// ---------------------------------------------------------------- phase 3
__global__ __launch_bounds__(256)
void k3_snow_replay(const float* __restrict__ P, const float* __restrict__ T,
                    const float* __restrict__ w_i, const float* __restrict__ w_l,
                    const float* __restrict__ w_s,
                    float* __restrict__ S)
{
    const int g     = blockIdx.x * blockDim.x + threadIdx.x;
    const int lane  = g & (LANES - 1);
    const int chunk = g >> 15;
    const int h     = lane & (NH - 1);
    const int site  = lane >> 4;

    const float melt = expf(w_s[h]) + 1.0f;
    const float gi   = 1.0f / (1.0f + expf(-w_i[h]));
    const float gl   = 1.0f / (1.0f + expf(-w_l[h]));
    const float c1   = 1.0f - gl;

    float s = g_sstart[g];
    float D = 0.0f;
    const int t0 = chunk * L;
    const float* Pp = P + site;
    const float* Tp = T + site;

    #pragma unroll 4
    for (int k = 0; k < L; k++) {
        const int t = t0 + k;
        const float Tk = __ldg(Tp + t * NS);
        const float Pk = __ldg(Pp + t * NS);
        const float sm   = fmaxf(Tk, 0.0f) * melt;
        const float m    = fminf(sm, s);
        const float pneg = (Tk < 0.0f) ? Pk : 0.0f;
        const float ppos = (Tk > 0.0f) ? Pk : 0.0f;
        const float sn   = s - m + pneg;
        const float xin  = (ppos + m) * gi;
        D = c1 * (D + xin);
        S[t * LANES + lane] = sn;
        s = sn;
    }
    g_D[g] = D;
}

// ---------------------------------------------------------------- phase 4
__global__ __launch_bounds__(256)
void k4_h_starts(const float* __restrict__ w_l)
{
    const int lane = blockIdx.x * blockDim.x + threadIdx.x;    // [0, LANES)
    const int h    = lane & (NH - 1);
    const float gl = 1.0f / (1.0f + expf(-w_l[h]));
    const float cL = powf(1.0f - gl, (float)L);

    float hh = 0.0f;
    #pragma unroll
    for (int c = 0; c < C; c++) {
        const int i = c * LANES + lane;
        g_hstart[i] = hh;
        hh = cL * hh + g_D[i];
    }
}

// ---------------------------------------------------------------- phase 5
__global__ __launch_bounds__(256)
void k5_final(const float* __restrict__ P, const float* __restrict__ T,
              const float* __restrict__ w_i, const float* __restrict__ w_o,
              const float* __restrict__ w_l, const float* __restrict__ w_s,
              float* __restrict__ Q, float* __restrict__ H)
{
    const int g     = blockIdx.x * blockDim.x + threadIdx.x;
    const int lane  = g & (LANES - 1);
    const int chunk = g >> 15;
    const int h     = lane & (NH - 1);
    const int site  = lane >> 4;

    const float melt = expf(w_s[h]) + 1.0f;
    const float gi   = 1.0f / (1.0f + expf(-w_i[h]));
    const float gl   = 1.0f / (1.0f + expf(-w_l[h]));

    // softmax over w_o
    float mx = w_o[0];
    #pragma unroll
    for (int j = 1; j < NH; j++) mx = fmaxf(mx, w_o[j]);
    float ssum = 0.0f;
    #pragma unroll
    for (int j = 0; j < NH; j++) ssum += expf(w_o[j] - mx);
    const float a = expf(w_o[h] - mx) / ssum;

    float s  = g_sstart[g];
    float hh = g_hstart[g];
    const int t0 = chunk * L;
    const float* Pp = P + site;
    const float* Tp = T + site;

    #pragma unroll 4
    for (int k = 0; k < L; k++) {
        const int t = t0 + k;
        const float Tk = __ldg(Tp + t * NS);
        const float Pk = __ldg(Pp + t * NS);
        const float sm   = fmaxf(Tk, 0.0f) * melt;
        const float m    = fminf(sm, s);
        const float pneg = (Tk < 0.0f) ? Pk : 0.0f;
        const float ppos = (Tk > 0.0f) ? Pk : 0.0f;
        const float sn   = s - m + pneg;
        const float xin  = (ppos + m) * gi;
        const float u    = xin + hh;
        const float q    = u * gl;
        const float hn   = u - q;

        H[t * LANES + lane] = hn;
        s  = sn;
        hh = hn;

        float qa = q * a;
        qa += __shfl_xor_sync(0xFFFFFFFFu, qa, 1);
        qa += __shfl_xor_sync(0xFFFFFFFFu, qa, 2);
        qa += __shfl_xor_sync(0xFFFFFFFFu, qa, 4);
        qa += __shfl_xor_sync(0xFFFFFFFFu, qa, 8);
        if (h == 0) Q[t * NS + site] = qa;
    }
}

// ---------------------------------------------------------------- launch
extern "C" void kernel_launch(void* const* d_in, const int* in_sizes, int n_in,
                              void* d_out, int out_size)
{
    const float* P   = (const float*)d_in[0];
    const float* T   = (const float*)d_in[1];
    const float* w_i = (const float*)d_in[2];
    const float* w_o = (const float*)d_in[3];
    const float* w_l = (const float*)d_in[4];
    const float* w_s = (const float*)d_in[5];

    float* Q = (float*)d_out;
    float* H = Q + (size_t)NT * NS;
    float* S = H + (size_t)NT * NS * NH;

    const int big  = (C * LANES) / 256;   // 1024 blocks
    const int smal = LANES / 256;         // 128 blocks

    k1_snow_compose<<<big, 256>>>(P, T, w_s);
    k2_snow_starts<<<smal, 256>>>();
    k3_snow_replay<<<big, 256>>>(P, T, w_i, w_l, w_s, S);
    k4_h_starts<<<smal, 256>>>(w_l);
    k5_final<<<big, 256>>>(P, T, w_i, w_o, w_l, w_s, Q, H);
}